// round 4
// baseline (speedup 1.0000x reference)
#include <cuda_runtime.h>

#define NK 5000
#define BB 512
#define TT 100

// sigmoid table: cols 0..3 packed as float4, col 4 (initial skill) separate,
// 16B-aligned so the state init/writeback can run as 128-bit transactions.
__device__ __align__(16) float4 g_tblA[NK];
__device__ __align__(16) float  g_tblL[NK];

__global__ void build_table(const float* __restrict__ logits) {
    int k = blockIdx.x * blockDim.x + threadIdx.x;
    if (k >= NK) return;
    const float* r = logits + k * 5;
    float4 v;
    v.x = 1.f / (1.f + __expf(-r[0]));
    v.y = 1.f / (1.f + __expf(-r[1]));
    v.z = 1.f / (1.f + __expf(-r[2]));
    v.w = 1.f / (1.f + __expf(-r[3]));
    g_tblA[k] = v;
    g_tblL[k] = 1.f / (1.f + __expf(-r[4]));
}

// One CTA per batch row. Per-row skill state lives in SMEM. All table gathers
// are state-independent and prefetched in parallel by 100 threads; the serial
// T-step recurrence runs on thread 0, software-pipelined so SMEM load latency
// is hidden behind the arithmetic of the previous step.
__global__ __launch_bounds__(256, 1) void bkt_kernel(
    const int* __restrict__ prev_kc,
    const int* __restrict__ curr_kc,
    const int* __restrict__ prev_corr,
    float* __restrict__ out)
{
    __shared__ __align__(16) float st[NK];   // 20 KB per-row skill state
    __shared__ float pre[TT][6];             // prefetched per-step table values
    __shared__ int   pks[TT];
    __shared__ int   cks[TT];
    __shared__ float pbuf[TT];

    const int b = blockIdx.x;
    const int tid = threadIdx.x;

    // Init state = sigmoid(logits[:,4]) — 128-bit, L2-broadcast (table is hot).
    {
        const float4* tl4 = (const float4*)g_tblL;
        float4* st4 = (float4*)st;
        for (int k = tid; k < NK / 4; k += 256) st4[k] = tl4[k];
    }

    // Parallel prefetch of all state-independent quantities.
    if (tid < TT) {
        const int t = tid;
        const int pk = prev_kc[b * TT + t];
        const int ck = curr_kc[b * TT + t];
        const int c  = prev_corr[b * TT + t];
        float4 pv = g_tblA[pk];
        float4 cv = g_tblA[ck];
        pre[t][0] = pv.x;                       // prev_p[0]
        pre[t][1] = pv.y;                       // prev_p[1]
        pre[t][2] = c ? pv.z : 1.f - pv.z;      // p_out[0]  (pch^c*(1-pch)^(1-c))
        pre[t][3] = c ? pv.w : 1.f - pv.w;      // p_out[1]
        pre[t][4] = cv.z;                       // curr_p[2]
        pre[t][5] = cv.w;                       // curr_p[3]
        pks[t] = pk;
        cks[t] = ck;
    }
    __syncthreads();

    // Serial recurrence, pipelined: both SMEM reads of an iteration are
    // issued before the iteration's store; register forwarding (select on
    // index equality) resolves the RAW hazards. Dependent chain per step is
    // just the divide + a few FMAs.
    if (tid == 0) {
        // t = 0: predict from initial state, no update.
        float cs0 = st[cks[0]];
        pbuf[0] = pre[0][4] * (1.f - cs0) + pre[0][5] * cs0;

        int   pk    = pks[1];
        float skill = st[pk];
        #pragma unroll 4
        for (int t = 1; t < TT; ++t) {
            const int   ck     = cks[t];
            const float csraw  = st[ck];                    // pre-store load
            const int   npk    = (t + 1 < TT) ? pks[t + 1] : 0;
            const float nskraw = st[npk];                   // pre-store load

            const float num  = pre[t][3] * skill;
            const float den  = fmaf(pre[t][2], 1.f - skill, num);
            const float filt = __fdividef(num, den);
            const float pred = pre[t][0] * (1.f - filt) + (1.f - pre[t][1]) * filt;
            st[pk] = pred;

            const float cs = (ck == pk) ? pred : csraw;     // forward past store
            pbuf[t] = pre[t][4] * (1.f - cs) + pre[t][5] * cs;

            skill = (npk == pk) ? pred : nskraw;            // forward past store
            pk = npk;
        }
    }
    __syncthreads();

    // Outputs: probs [B,T] at offset 0, final state [B,NK] after it.
    if (tid < TT) out[b * TT + tid] = pbuf[tid];
    {
        const float4* st4 = (const float4*)st;
        float4* so4 = (float4*)(out + BB * TT + b * NK);    // 16B-aligned
        for (int k = tid; k < NK / 4; k += 256) so4[k] = st4[k];
    }
}

extern "C" void kernel_launch(void* const* d_in, const int* in_sizes, int n_in,
                              void* d_out, int out_size) {
    const int*   prev_kc   = (const int*)d_in[0];
    const int*   curr_kc   = (const int*)d_in[1];
    const int*   prev_corr = (const int*)d_in[2];
    const float* logits    = (const float*)d_in[3];
    float*       out       = (float*)d_out;

    build_table<<<(NK + 255) / 256, 256>>>(logits);
    bkt_kernel<<<BB, 256>>>(prev_kc, curr_kc, prev_corr, out);
}

// round 5
// speedup vs baseline: 1.5075x; 1.5075x over previous
#include <cuda_runtime.h>

#define NK 5000
#define BB 512
#define TT 100

// sigmoid table: cols 0..3 packed as float4, col 4 (initial skill) separate,
// 16B-aligned for 128-bit init/writeback transactions.
__device__ __align__(16) float4 g_tblA[NK];
__device__ __align__(16) float  g_tblL[NK];

__global__ void build_table(const float* __restrict__ logits) {
    int k = blockIdx.x * blockDim.x + threadIdx.x;
    if (k >= NK) return;
    const float* r = logits + k * 5;
    float4 v;
    v.x = 1.f / (1.f + __expf(-r[0]));
    v.y = 1.f / (1.f + __expf(-r[1]));
    v.z = 1.f / (1.f + __expf(-r[2]));
    v.w = 1.f / (1.f + __expf(-r[3]));
    g_tblA[k] = v;
    g_tblL[k] = 1.f / (1.f + __expf(-r[4]));
}

// One CTA per batch row.
//   Phase 1 (parallel): init 20KB SMEM state; prefetch + pre-reduce all
//     state-independent per-step constants into packed SMEM records.
//   Phase 2: thread 0 runs the serial chain (dep chain ~= FMA->RCP->MUL->ADD
//     per step) and emits probs via direct STG; warps 1..7 simultaneously
//     stream the INIT state to gmem (final state == init except at pks).
//   Phase 3: 99 threads overwrite the touched state entries with final values.
__global__ __launch_bounds__(256, 1) void bkt_kernel(
    const int* __restrict__ prev_kc,
    const int* __restrict__ curr_kc,
    const int* __restrict__ prev_corr,
    float* __restrict__ out)
{
    __shared__ __align__(16) float st[NK];     // per-row skill state (20 KB)
    __shared__ __align__(16) float4 preA[TT];  // {p2, p3-p2, a, bcoef*p3}
    __shared__ __align__(8)  float2 preB[TT];  // {c4, c5-c4}
    __shared__ __align__(8)  int2   idx[TT];   // {pks[t+1], cks[t]}

    const int b = blockIdx.x;
    const int tid = threadIdx.x;

    // --- state init: L2-broadcast of sigmoid(logits[:,4]), 128-bit ---
    {
        const float4* tl4 = (const float4*)g_tblL;
        float4* st4 = (float4*)st;
        #pragma unroll
        for (int k = tid; k < NK / 4; k += 256) st4[k] = tl4[k];
    }

    // --- parallel prefetch + constant pre-reduction ---
    if (tid < TT) {
        const int t = tid;
        const int pk = prev_kc[b * TT + t];
        const int ck = curr_kc[b * TT + t];
        const int c  = prev_corr[b * TT + t];
        float4 pv = g_tblA[pk];
        float4 cv = g_tblA[ck];
        const float p2 = c ? pv.z : 1.f - pv.z;   // p_out[0]
        const float p3 = c ? pv.w : 1.f - pv.w;   // p_out[1]
        const float a  = pv.x;                    // prev_p[0]
        const float bc = 1.f - pv.y - pv.x;       // (1-prev1) - prev0
        preA[t] = make_float4(p2, p3 - p2, a, bc * p3);
        preB[t] = make_float2(cv.z, cv.w - cv.z);
        idx[t].y = ck;
        if (t > 0) idx[t - 1].x = pk;             // pks[t] -> idx[t-1].x
        if (t == TT - 1) idx[TT - 1].x = 0;       // dummy carry-out
    }
    __syncthreads();

    float* stateOut = out + BB * TT + b * NK;

    if (tid == 0) {
        // t = 0: predict from initial state, no update.
        {
            const float cs0 = st[idx[0].y];
            const float2 P0 = preB[0];
            out[b * TT + 0] = fmaf(cs0, P0.y, P0.x);
        }
        int   pk    = idx[0].x;        // pks[1]
        float skill = st[pk];
        #pragma unroll 4
        for (int t = 1; t < TT; ++t) {
            const int2   I      = idx[t];          // {pks[t+1], cks[t]}
            const float  csraw  = st[I.y];         // pre-store loads
            const float  nskraw = st[I.x];
            const float4 C      = preA[t];
            const float2 P      = preB[t];

            // dependent chain: fma -> rcp -> mul -> add
            const float den  = fmaf(C.y, skill, C.x);
            const float m    = C.w * skill;                 // off-chain vs rcp
            const float pred = C.z + __fdividef(m, den);
            st[pk] = pred;

            const float cs = (I.y == pk) ? pred : csraw;    // forward past store
            out[b * TT + t] = fmaf(cs, P.y, P.x);           // off-chain STG

            skill = (I.x == pk) ? pred : nskraw;            // forward past store
            pk = I.x;
        }
    } else if (tid >= 32) {
        // Overlap: stream the INIT state to gmem while the chain runs.
        const float4* tl4 = (const float4*)g_tblL;
        float4* so4 = (float4*)stateOut;                    // 16B-aligned
        for (int k = tid - 32; k < NK / 4; k += 224) so4[k] = tl4[k];
    }
    __syncthreads();

    // Fix-up: only entries pks[1..99] differ from init; st holds final values.
    if (tid < TT - 1) {
        const int p = idx[tid].x;      // pks[tid+1]
        stateOut[p] = st[p];
    }
}

extern "C" void kernel_launch(void* const* d_in, const int* in_sizes, int n_in,
                              void* d_out, int out_size) {
    const int*   prev_kc   = (const int*)d_in[0];
    const int*   curr_kc   = (const int*)d_in[1];
    const int*   prev_corr = (const int*)d_in[2];
    const float* logits    = (const float*)d_in[3];
    float*       out       = (float*)d_out;

    build_table<<<(NK + 255) / 256, 256>>>(logits);
    bkt_kernel<<<BB, 256>>>(prev_kc, curr_kc, prev_corr, out);
}

// round 7
// speedup vs baseline: 1.5403x; 1.0218x over previous
#include <cuda_runtime.h>

#define NK 5000
#define BB 512
#define TT 100

// Only the initial-skill column (sigmoid of logits[:,4]) is materialized as a
// table — it's the bulk writeback stream. Everything else is computed from
// logits directly by the per-CTA prefetch threads.
__device__ __align__(16) float g_tblL[NK];

__device__ __forceinline__ float sigm(float x) {
    return 1.f / (1.f + __expf(-x));
}

__global__ void build_table(const float* __restrict__ logits) {
    int k = blockIdx.x * blockDim.x + threadIdx.x;
    if (k >= NK) return;
    g_tblL[k] = sigm(logits[k * 5 + 4]);
}

// One CTA per batch row.
//   Prefetch (parallel, 100 threads): gather logits rows for pk/ck, compute
//     sigmoids + pre-reduced chain constants, and SPARSELY init st[] at just
//     the <=200 indices the chain touches (init value = sigmoid(col4)).
//   Chain (thread 0): serial T-step recurrence; dep chain FMA->RCP->MUL->ADD
//     per step; probs emitted via direct STG.
//   Writeback (warps 1..7, overlapped): stream INIT state (g_tblL) to gmem;
//     final state differs from init only at pks, fixed up after the chain.
__global__ __launch_bounds__(256, 1) void bkt_kernel(
    const int* __restrict__ prev_kc,
    const int* __restrict__ curr_kc,
    const int* __restrict__ prev_corr,
    const float* __restrict__ logits,
    float* __restrict__ out)
{
    __shared__ __align__(16) float st[NK];     // sparsely-used skill state
    __shared__ __align__(16) float4 preA[TT];  // {p2, p3-p2, a, bcoef*p3}
    __shared__ __align__(8)  float2 preB[TT];  // {c4, c5-c4}
    __shared__ __align__(8)  int2   idx[TT];   // {pks[t+1], cks[t]}

    const int b = blockIdx.x;
    const int tid = threadIdx.x;

    // --- parallel prefetch: gathers, sigmoids, constant pre-reduction,
    //     and sparse state init (same-value write races are benign) ---
    if (tid < TT) {
        const int t = tid;
        const int pk = prev_kc[b * TT + t];
        const int ck = curr_kc[b * TT + t];
        const int c  = prev_corr[b * TT + t];
        const float* rp = logits + pk * 5;
        const float* cp = logits + ck * 5;

        const float pvx = sigm(rp[0]);
        const float pvy = sigm(rp[1]);
        const float pvz = sigm(rp[2]);
        const float pvw = sigm(rp[3]);
        st[pk] = sigm(rp[4]);                   // sparse init
        const float cvz = sigm(cp[2]);
        const float cvw = sigm(cp[3]);
        st[ck] = sigm(cp[4]);                   // sparse init

        const float p2 = c ? pvz : 1.f - pvz;   // p_out[0]
        const float p3 = c ? pvw : 1.f - pvw;   // p_out[1]
        const float bc = 1.f - pvy - pvx;       // (1-prev1) - prev0
        preA[t] = make_float4(p2, p3 - p2, pvx, bc * p3);
        preB[t] = make_float2(cvz, cvw - cvz);
        idx[t].y = ck;
        if (t > 0) idx[t - 1].x = pk;           // pks[t] -> idx[t-1].x
        if (t == TT - 1) idx[TT - 1].x = pk;    // harmless carry-out (inited)
    }
    __syncthreads();

    float* stateOut = out + BB * TT + b * NK;

    if (tid == 0) {
        // t = 0: predict from initial state, no update.
        {
            const float cs0 = st[idx[0].y];
            const float2 P0 = preB[0];
            out[b * TT + 0] = fmaf(cs0, P0.y, P0.x);
        }
        int   pk    = idx[0].x;        // pks[1]
        float skill = st[pk];
        #pragma unroll 4
        for (int t = 1; t < TT; ++t) {
            const int2   I      = idx[t];          // {pks[t+1], cks[t]}
            const float  csraw  = st[I.y];         // pre-store loads: latency
            const float  nskraw = st[I.x];         //   hides under rcp chain
            const float4 C      = preA[t];
            const float2 P      = preB[t];

            // dependent chain: fma -> rcp -> mul -> add
            const float den  = fmaf(C.y, skill, C.x);
            const float m    = C.w * skill;                 // off-chain vs rcp
            const float pred = C.z + __fdividef(m, den);
            st[pk] = pred;

            const float cs = (I.y == pk) ? pred : csraw;    // forward past store
            out[b * TT + t] = fmaf(cs, P.y, P.x);           // off-chain STG

            skill = (I.x == pk) ? pred : nskraw;            // forward past store
            pk = I.x;
        }
    } else if (tid >= 32) {
        // Overlap with the chain: stream the INIT state to gmem (L2-broadcast
        // of the shared 20KB table; final state == init except at pks).
        const float4* tl4 = (const float4*)g_tblL;
        float4* so4 = (float4*)stateOut;                    // 16B-aligned
        for (int k = tid - 32; k < NK / 4; k += 224) so4[k] = tl4[k];
    }
    __syncthreads();

    // Fix-up: overwrite the <=99 entries the chain actually updated.
    if (tid < TT - 1) {
        const int p = idx[tid].x;      // pks[tid+1]
        stateOut[p] = st[p];
    }
}

extern "C" void kernel_launch(void* const* d_in, const int* in_sizes, int n_in,
                              void* d_out, int out_size) {
    const int*   prev_kc   = (const int*)d_in[0];
    const int*   curr_kc   = (const int*)d_in[1];
    const int*   prev_corr = (const int*)d_in[2];
    const float* logits    = (const float*)d_in[3];
    float*       out       = (float*)d_out;

    build_table<<<(NK + 255) / 256, 256>>>(logits);
    bkt_kernel<<<BB, 256>>>(prev_kc, curr_kc, prev_corr, logits, out);
}